// round 1
// baseline (speedup 1.0000x reference)
#include <cuda_runtime.h>
#include <cuda_bf16.h>
#include <cstdint>

#define Nn 50000
#define Ee 1600000
#define Hh 64
#define INC 7
#define ED 4
#define Gg 256
#define FCH 128
#define NC 2

// ---------------- device scratch (allocation-free rule: __device__ globals) ---------
__device__ __align__(16) float g_xl[Nn * Hh];
__device__ __align__(16) float g_xr[Nn * Hh];
__device__ __align__(16) float g_agg[Nn * Hh];
__device__ __align__(16) float g_h[Nn * Hh];
__device__ float g_den[Nn];
__device__ float g_pool[Gg * Hh];
__device__ float g_cnt[Gg];

// ---------------- projections: xl = x@Wl+bl, xr = x@Wr+br; zero accumulators -------
template <int INsz, bool USE_GH>
__global__ void proj_kernel(const float* __restrict__ x,
                            const float* __restrict__ Wl, const float* __restrict__ bl,
                            const float* __restrict__ Wr, const float* __restrict__ br) {
    int idx = blockIdx.x * blockDim.x + threadIdx.x;
    if (idx >= Nn * Hh) return;
    int n = idx >> 6;
    int h = idx & 63;
    const float* xrow = USE_GH ? (g_h + n * INsz) : (x + n * INsz);
    float al = bl[h];
    float ar = br[h];
#pragma unroll
    for (int k = 0; k < INsz; k++) {
        float xv = xrow[k];
        al = fmaf(xv, Wl[k * Hh + h], al);
        ar = fmaf(xv, Wr[k * Hh + h], ar);
    }
    g_xl[idx] = al;
    g_xr[idx] = ar;
    g_agg[idx] = 0.0f;
    if (h == 0) g_den[n] = 0.0f;
}

// ---------------- fused edge pass: score -> exp -> weighted scatter ----------------
// 16 lanes per edge, each lane owns 4 heads. 2 edges per warp, 16 edges per block.
__global__ __launch_bounds__(256) void edge_kernel(const int* __restrict__ ei,
                                                   const float* __restrict__ ea,
                                                   const float* __restrict__ We,   // [ED][Hh]
                                                   const float* __restrict__ att)  // [Hh]
{
    __shared__ float sWe[Hh * ED];  // [h][k]
    __shared__ float sAtt[Hh];
    int t = threadIdx.x;
    if (t < Hh) {
        sAtt[t] = att[t];
#pragma unroll
        for (int k = 0; k < ED; k++) sWe[t * ED + k] = We[k * Hh + t];
    }
    __syncthreads();

    int warp = (blockIdx.x * (blockDim.x >> 5)) + (t >> 5);
    int e = warp * 2 + ((t >> 4) & 1);
    if (e >= Ee) return;
    int sl = t & 15;
    int h = sl * 4;

    int src = ei[e];
    int dst = ei[Ee + e];
    float4 eav = *reinterpret_cast<const float4*>(ea + e * 4);
    float4 xl4 = *reinterpret_cast<const float4*>(g_xl + src * Hh + h);
    float4 xr4 = *reinterpret_cast<const float4*>(g_xr + dst * Hh + h);

    float xlv[4] = {xl4.x, xl4.y, xl4.z, xl4.w};
    float xrv[4] = {xr4.x, xr4.y, xr4.z, xr4.w};

    float p = 0.0f;
#pragma unroll
    for (int j = 0; j < 4; j++) {
        int hh = h + j;
        float pre = xlv[j] + xrv[j];
        pre = fmaf(eav.x, sWe[hh * ED + 0], pre);
        pre = fmaf(eav.y, sWe[hh * ED + 1], pre);
        pre = fmaf(eav.z, sWe[hh * ED + 2], pre);
        pre = fmaf(eav.w, sWe[hh * ED + 3], pre);
        pre = pre > 0.0f ? pre : 0.2f * pre;    // LeakyReLU(0.2)
        p = fmaf(pre, sAtt[hh], p);
    }
    // reduce across the 16 lanes of this edge (xor pattern stays inside the group)
    p += __shfl_xor_sync(0xffffffffu, p, 8);
    p += __shfl_xor_sync(0xffffffffu, p, 4);
    p += __shfl_xor_sync(0xffffffffu, p, 2);
    p += __shfl_xor_sync(0xffffffffu, p, 1);

    float ex = __expf(p);  // softmax without max-shift: mathematically identical

    float* dp = g_agg + dst * Hh + h;
    asm volatile("red.global.add.v4.f32 [%0], {%1, %2, %3, %4};"
                 :: "l"(dp), "f"(xlv[0] * ex), "f"(xlv[1] * ex),
                    "f"(xlv[2] * ex), "f"(xlv[3] * ex)
                 : "memory");
    if (sl == 0) atomicAdd(&g_den[dst], ex);
}

// ---------------- finalize: h = elu(agg/den + bias); optionally zero pool ----------
__global__ void finalize_kernel(const float* __restrict__ bias, int zero_pool) {
    int idx = blockIdx.x * blockDim.x + threadIdx.x;
    if (idx >= Nn * Hh) return;
    int n = idx >> 6;
    int h = idx & 63;
    float v = g_agg[idx] / (g_den[n] + 1e-16f) + bias[h];
    g_h[idx] = v > 0.0f ? v : expm1f(v);
    if (zero_pool) {
        if (idx < Gg * Hh) g_pool[idx] = 0.0f;
        if (idx < Gg) g_cnt[idx] = 0.0f;
    }
}

// ---------------- global mean pool (sum + count via atomics) -----------------------
__global__ void pool_kernel(const int* __restrict__ batch) {
    int idx = blockIdx.x * blockDim.x + threadIdx.x;
    if (idx >= Nn * Hh) return;
    int n = idx >> 6;
    int h = idx & 63;
    int b = batch[n];
    atomicAdd(&g_pool[b * Hh + h], g_h[idx]);
    if (h == 0) atomicAdd(&g_cnt[b], 1.0f);
}

// ---------------- head: mean -> fc1(relu) -> fc2 -> log_softmax --------------------
__global__ __launch_bounds__(FCH) void head_kernel(const float* __restrict__ fc1w,
                                                   const float* __restrict__ fc1b,
                                                   const float* __restrict__ fc2w,
                                                   const float* __restrict__ fc2b,
                                                   float* __restrict__ out) {
    __shared__ float sg[Hh];
    __shared__ float sfc[FCH];
    __shared__ float slog[NC];
    int g = blockIdx.x;
    int t = threadIdx.x;
    if (t < Hh) {
        float inv = 1.0f / fmaxf(g_cnt[g], 1.0f);
        sg[t] = g_pool[g * Hh + t] * inv;
    }
    __syncthreads();
    float a = fc1b[t];
#pragma unroll 8
    for (int k = 0; k < Hh; k++) a = fmaf(sg[k], fc1w[k * FCH + t], a);
    sfc[t] = fmaxf(a, 0.0f);
    __syncthreads();
    if (t < NC) {
        float z = fc2b[t];
#pragma unroll 8
        for (int k = 0; k < FCH; k++) z = fmaf(sfc[k], fc2w[k * NC + t], z);
        slog[t] = z;
    }
    __syncthreads();
    if (t == 0) {
        float l0 = slog[0], l1 = slog[1];
        float m = fmaxf(l0, l1);
        float lse = m + logf(expf(l0 - m) + expf(l1 - m));
        out[g * NC + 0] = l0 - lse;
        out[g * NC + 1] = l1 - lse;
    }
}

// -----------------------------------------------------------------------------------
extern "C" void kernel_launch(void* const* d_in, const int* in_sizes, int n_in,
                              void* d_out, int out_size) {
    const float* x      = (const float*)d_in[0];
    const int*   ei     = (const int*)d_in[1];
    const float* ea     = (const float*)d_in[2];
    const int*   batch  = (const int*)d_in[3];
    const float* Wl0    = (const float*)d_in[4];
    const float* bl0    = (const float*)d_in[5];
    const float* Wr0    = (const float*)d_in[6];
    const float* br0    = (const float*)d_in[7];
    const float* We0    = (const float*)d_in[8];
    const float* att0   = (const float*)d_in[9];
    const float* bias0  = (const float*)d_in[10];
    const float* Wl1    = (const float*)d_in[11];
    const float* bl1    = (const float*)d_in[12];
    const float* Wr1    = (const float*)d_in[13];
    const float* br1    = (const float*)d_in[14];
    const float* We1    = (const float*)d_in[15];
    const float* att1   = (const float*)d_in[16];
    const float* bias1  = (const float*)d_in[17];
    const float* fc1w   = (const float*)d_in[18];
    const float* fc1b   = (const float*)d_in[19];
    const float* fc2w   = (const float*)d_in[20];
    const float* fc2b   = (const float*)d_in[21];
    float* out = (float*)d_out;

    const int pgrid = (Nn * Hh + 255) / 256;       // 12500 blocks
    const int egrid = (Ee + 15) / 16;              // 100000 blocks (exact: no partial warps)

    // Layer 0
    proj_kernel<INC, false><<<pgrid, 256>>>(x, Wl0, bl0, Wr0, br0);
    edge_kernel<<<egrid, 256>>>(ei, ea, We0, att0);
    finalize_kernel<<<pgrid, 256>>>(bias0, 0);
    // Layer 1
    proj_kernel<Hh, true><<<pgrid, 256>>>(nullptr, Wl1, bl1, Wr1, br1);
    edge_kernel<<<egrid, 256>>>(ei, ea, We1, att1);
    finalize_kernel<<<pgrid, 256>>>(bias1, 1);
    // Pool + head
    pool_kernel<<<pgrid, 256>>>(batch);
    head_kernel<<<Gg, FCH>>>(fc1w, fc1b, fc2w, fc2b, out);
}

// round 2
// speedup vs baseline: 1.8901x; 1.8901x over previous
#include <cuda_runtime.h>
#include <cuda_bf16.h>
#include <cstdint>

#define Nn 50000
#define Ee 1600000
#define Hh 64
#define INC 7
#define ED 4
#define Gg 256
#define FCH 128
#define NC 2
#define CH 32          // edges per 16-lane half in sorted edge pass

// ---------------- device scratch ----------------------------------------------------
__device__ __align__(16) float g_xl[Nn * Hh];
__device__ __align__(16) float g_xr[Nn * Hh];
__device__ __align__(16) float g_agg[Nn * Hh];
__device__ float g_den[Nn];
__device__ float g_pool[Gg * Hh];
__device__ float g_cnt[Gg];
__device__ int   g_cur[Nn];                 // histogram -> exclusive offsets -> cursors
__device__ __align__(16) int2   g_sd[Ee];   // sorted (src,dst) pairs
__device__ __align__(16) float4 g_eaS[Ee];  // edge_attr permuted to sorted order

// ---------------- proj layer 0 (in=7) + zero accumulators --------------------------
__global__ void proj0_kernel(const float* __restrict__ x,
                             const float* __restrict__ Wl, const float* __restrict__ bl,
                             const float* __restrict__ Wr, const float* __restrict__ br) {
    int idx = blockIdx.x * blockDim.x + threadIdx.x;
    if (idx >= Nn * Hh) return;
    int n = idx >> 6;
    int h = idx & 63;
    const float* xrow = x + n * INC;
    float al = bl[h];
    float ar = br[h];
#pragma unroll
    for (int k = 0; k < INC; k++) {
        float xv = xrow[k];
        al = fmaf(xv, Wl[k * Hh + h], al);
        ar = fmaf(xv, Wr[k * Hh + h], ar);
    }
    g_xl[idx] = al;
    g_xr[idx] = ar;
    g_agg[idx] = 0.0f;
    if (h == 0) { g_den[n] = 0.0f; g_cur[n] = 0; }
}

// ---------------- counting sort: histogram ------------------------------------------
__global__ void hist_kernel(const int* __restrict__ ei) {
    int e = blockIdx.x * blockDim.x + threadIdx.x;
    if (e >= Ee) return;
    atomicAdd(&g_cur[ei[Ee + e]], 1);
}

// ---------------- single-block exclusive scan (also zeros pool buffers) ------------
__global__ __launch_bounds__(1024) void scan_kernel() {
    __shared__ int sp[1024];
    int t = threadIdx.x;
    const int CHK = (Nn + 1023) / 1024;   // 49
    int base = t * CHK;
    int s = 0;
    for (int i = 0; i < CHK; i++) {
        int j = base + i;
        if (j < Nn) s += g_cur[j];
    }
    sp[t] = s;
    __syncthreads();
    for (int off = 1; off < 1024; off <<= 1) {
        int v = (t >= off) ? sp[t - off] : 0;
        __syncthreads();
        sp[t] += v;
        __syncthreads();
    }
    int run = sp[t] - s;   // exclusive prefix of this thread's chunk
    for (int i = 0; i < CHK; i++) {
        int j = base + i;
        if (j < Nn) {
            int c = g_cur[j];
            g_cur[j] = run;
            run += c;
        }
    }
    // zero pool accumulators (used much later; stream order protects us)
    for (int i = t; i < Gg * Hh; i += 1024) g_pool[i] = 0.0f;
    if (t < Gg) g_cnt[t] = 0.0f;
}

// ---------------- counting sort: scatter --------------------------------------------
__global__ void scatter_kernel(const int* __restrict__ ei, const float* __restrict__ ea) {
    int e = blockIdx.x * blockDim.x + threadIdx.x;
    if (e >= Ee) return;
    int s = ei[e];
    int d = ei[Ee + e];
    int pos = atomicAdd(&g_cur[d], 1);
    g_sd[pos] = make_int2(s, d);
    g_eaS[pos] = *reinterpret_cast<const float4*>(ea + 4 * e);
}

// ---------------- fused edge pass over dst-sorted edges ----------------------------
// 16 lanes per edge-stream (each lane owns 4 heads); each 16-lane half walks CH
// contiguous sorted edges, accumulating in registers, flushing once per dst run.
__global__ __launch_bounds__(256) void edge_sorted_kernel(const float* __restrict__ We,
                                                          const float* __restrict__ att) {
    __shared__ float sWe[Hh * ED];
    __shared__ float sAtt[Hh];
    int t = threadIdx.x;
    if (t < Hh) {
        sAtt[t] = att[t];
#pragma unroll
        for (int k = 0; k < ED; k++) sWe[t * ED + k] = We[k * Hh + t];
    }
    __syncthreads();

    int lid = t & 31;
    int half = ((blockIdx.x * (blockDim.x >> 5) + (t >> 5)) << 1) + (lid >> 4);
    int sl = lid & 15;
    int h = sl * 4;
    int base = half * CH;
    if (base >= Ee) return;

    // cache this lane's 4 attention/We rows in registers
    float at[4], wk[4][4];
#pragma unroll
    for (int j = 0; j < 4; j++) {
        at[j] = sAtt[h + j];
#pragma unroll
        for (int k = 0; k < ED; k++) wk[j][k] = sWe[(h + j) * ED + k];
    }

    int cur = -1;
    float4 xr = make_float4(0.f, 0.f, 0.f, 0.f);
    float4 acc = make_float4(0.f, 0.f, 0.f, 0.f);
    float den = 0.0f;

#pragma unroll 1
    for (int i = 0; i < CH; i++) {
        int e = base + i;
        int2 sd = g_sd[e];
        if (sd.y != cur) {
            if (cur >= 0) {
                float* dp = g_agg + ((long)cur << 6) + h;
                asm volatile("red.global.add.v4.f32 [%0], {%1, %2, %3, %4};"
                             :: "l"(dp), "f"(acc.x), "f"(acc.y), "f"(acc.z), "f"(acc.w)
                             : "memory");
                if (sl == 0)
                    asm volatile("red.global.add.f32 [%0], %1;"
                                 :: "l"(g_den + cur), "f"(den) : "memory");
            }
            cur = sd.y;
            xr = *reinterpret_cast<const float4*>(g_xr + ((long)cur << 6) + h);
            acc = make_float4(0.f, 0.f, 0.f, 0.f);
            den = 0.0f;
        }
        float4 xl = *reinterpret_cast<const float4*>(g_xl + ((long)sd.x << 6) + h);
        float4 ea4 = g_eaS[e];

        float p = 0.0f;
        {
            float pre = xl.x + xr.x;
            pre = fmaf(ea4.x, wk[0][0], pre); pre = fmaf(ea4.y, wk[0][1], pre);
            pre = fmaf(ea4.z, wk[0][2], pre); pre = fmaf(ea4.w, wk[0][3], pre);
            pre = pre > 0.0f ? pre : 0.2f * pre;
            p = fmaf(pre, at[0], p);
            pre = xl.y + xr.y;
            pre = fmaf(ea4.x, wk[1][0], pre); pre = fmaf(ea4.y, wk[1][1], pre);
            pre = fmaf(ea4.z, wk[1][2], pre); pre = fmaf(ea4.w, wk[1][3], pre);
            pre = pre > 0.0f ? pre : 0.2f * pre;
            p = fmaf(pre, at[1], p);
            pre = xl.z + xr.z;
            pre = fmaf(ea4.x, wk[2][0], pre); pre = fmaf(ea4.y, wk[2][1], pre);
            pre = fmaf(ea4.z, wk[2][2], pre); pre = fmaf(ea4.w, wk[2][3], pre);
            pre = pre > 0.0f ? pre : 0.2f * pre;
            p = fmaf(pre, at[2], p);
            pre = xl.w + xr.w;
            pre = fmaf(ea4.x, wk[3][0], pre); pre = fmaf(ea4.y, wk[3][1], pre);
            pre = fmaf(ea4.z, wk[3][2], pre); pre = fmaf(ea4.w, wk[3][3], pre);
            pre = pre > 0.0f ? pre : 0.2f * pre;
            p = fmaf(pre, at[3], p);
        }
        p += __shfl_xor_sync(0xffffffffu, p, 8);
        p += __shfl_xor_sync(0xffffffffu, p, 4);
        p += __shfl_xor_sync(0xffffffffu, p, 2);
        p += __shfl_xor_sync(0xffffffffu, p, 1);

        float ex = __expf(p);   // softmax without max-shift: identical result
        acc.x = fmaf(xl.x, ex, acc.x);
        acc.y = fmaf(xl.y, ex, acc.y);
        acc.z = fmaf(xl.z, ex, acc.z);
        acc.w = fmaf(xl.w, ex, acc.w);
        den += ex;
    }
    if (cur >= 0) {
        float* dp = g_agg + ((long)cur << 6) + h;
        asm volatile("red.global.add.v4.f32 [%0], {%1, %2, %3, %4};"
                     :: "l"(dp), "f"(acc.x), "f"(acc.y), "f"(acc.z), "f"(acc.w)
                     : "memory");
        if (sl == 0)
            asm volatile("red.global.add.f32 [%0], %1;"
                         :: "l"(g_den + cur), "f"(den) : "memory");
    }
}

// ---------------- proj layer 1: tiled GEMM, elu(layer0) fused into X load ----------
// X[n][k] = elu(g_agg[n][k]/den[n] + bias0[k]);  out cols 0..63 -> g_xl, 64..127 -> g_xr
// Epilogue zeroes g_agg/g_den for this row tile (only this block touches those rows).
__global__ __launch_bounds__(256) void proj1_gemm_kernel(const float* __restrict__ Wl,
                                                         const float* __restrict__ bl,
                                                         const float* __restrict__ Wr,
                                                         const float* __restrict__ br,
                                                         const float* __restrict__ bias0) {
    __shared__ float sXT[32][68];   // [k][node], stride 68 keeps float4 alignment
    __shared__ float sW[32][128];   // [k][col]
    int t = threadIdx.x;
    int m0 = blockIdx.x * 64;
    int tm = t & 15;      // node group (4 nodes)
    int tn = t >> 4;      // col group (8 cols)
    float acc[4][8];
#pragma unroll
    for (int i = 0; i < 4; i++)
#pragma unroll
        for (int j = 0; j < 8; j++) acc[i][j] = 0.0f;

    for (int k0 = 0; k0 < 64; k0 += 32) {
        // load+transform X chunk: 64 nodes x 32 k
#pragma unroll
        for (int i = 0; i < 8; i++) {
            int idx = t + i * 256;
            int r = idx >> 5;
            int kk = idx & 31;
            int n = m0 + r;
            float v = 0.0f;
            if (n < Nn) {
                float a = g_agg[n * 64 + k0 + kk];
                float vv = a / (g_den[n] + 1e-16f) + bias0[k0 + kk];
                v = vv > 0.0f ? vv : expm1f(vv);
            }
            sXT[kk][r] = v;
        }
        // load W chunk: 32 k x 128 cols (Wl || Wr)
#pragma unroll
        for (int i = 0; i < 16; i++) {
            int idx = t + i * 256;
            int kk = idx >> 7;
            int n = idx & 127;
            sW[kk][n] = (n < 64) ? Wl[(k0 + kk) * 64 + n] : Wr[(k0 + kk) * 64 + (n - 64)];
        }
        __syncthreads();
#pragma unroll
        for (int kk = 0; kk < 32; kk++) {
            float4 a = *reinterpret_cast<const float4*>(&sXT[kk][tm * 4]);
            float4 b0 = *reinterpret_cast<const float4*>(&sW[kk][tn * 8]);
            float4 b1 = *reinterpret_cast<const float4*>(&sW[kk][tn * 8 + 4]);
            float av[4] = {a.x, a.y, a.z, a.w};
            float bv[8] = {b0.x, b0.y, b0.z, b0.w, b1.x, b1.y, b1.z, b1.w};
#pragma unroll
            for (int i = 0; i < 4; i++)
#pragma unroll
                for (int j = 0; j < 8; j++)
                    acc[i][j] = fmaf(av[i], bv[j], acc[i][j]);
        }
        __syncthreads();
    }
    // epilogue: bias + store
#pragma unroll
    for (int i = 0; i < 4; i++) {
        int n = m0 + tm * 4 + i;
        if (n >= Nn) break;
#pragma unroll
        for (int j = 0; j < 8; j++) {
            int c = tn * 8 + j;
            if (c < 64) g_xl[n * 64 + c] = acc[i][j] + bl[c];
            else        g_xr[n * 64 + (c - 64)] = acc[i][j] + br[c - 64];
        }
    }
    // zero accumulators for layer 1 (this block owns rows m0..m0+63)
#pragma unroll
    for (int i = 0; i < 16; i++) {
        int idx = t + i * 256;
        int r = idx >> 6;
        int k = idx & 63;
        int n = m0 + r;
        if (n < Nn) g_agg[n * 64 + k] = 0.0f;
    }
    if (t < 64 && m0 + t < Nn) g_den[m0 + t] = 0.0f;
}

// ---------------- pool with finalize-1 fused (elu before atomics) ------------------
__global__ void pool_kernel(const int* __restrict__ batch, const float* __restrict__ bias1) {
    int idx = blockIdx.x * blockDim.x + threadIdx.x;
    if (idx >= Nn * Hh) return;
    int n = idx >> 6;
    int h = idx & 63;
    float v = g_agg[idx] / (g_den[n] + 1e-16f) + bias1[h];
    v = v > 0.0f ? v : expm1f(v);
    int b = batch[n];
    atomicAdd(&g_pool[b * Hh + h], v);
    if (h == 0) atomicAdd(&g_cnt[b], 1.0f);
}

// ---------------- head: mean -> fc1(relu) -> fc2 -> log_softmax --------------------
__global__ __launch_bounds__(FCH) void head_kernel(const float* __restrict__ fc1w,
                                                   const float* __restrict__ fc1b,
                                                   const float* __restrict__ fc2w,
                                                   const float* __restrict__ fc2b,
                                                   float* __restrict__ out) {
    __shared__ float sg[Hh];
    __shared__ float sfc[FCH];
    __shared__ float slog[NC];
    int g = blockIdx.x;
    int t = threadIdx.x;
    if (t < Hh) {
        float inv = 1.0f / fmaxf(g_cnt[g], 1.0f);
        sg[t] = g_pool[g * Hh + t] * inv;
    }
    __syncthreads();
    float a = fc1b[t];
#pragma unroll 8
    for (int k = 0; k < Hh; k++) a = fmaf(sg[k], fc1w[k * FCH + t], a);
    sfc[t] = fmaxf(a, 0.0f);
    __syncthreads();
    if (t < NC) {
        float z = fc2b[t];
#pragma unroll 8
        for (int k = 0; k < FCH; k++) z = fmaf(sfc[k], fc2w[k * NC + t], z);
        slog[t] = z;
    }
    __syncthreads();
    if (t == 0) {
        float l0 = slog[0], l1 = slog[1];
        float m = fmaxf(l0, l1);
        float lse = m + logf(expf(l0 - m) + expf(l1 - m));
        out[g * NC + 0] = l0 - lse;
        out[g * NC + 1] = l1 - lse;
    }
}

// -----------------------------------------------------------------------------------
extern "C" void kernel_launch(void* const* d_in, const int* in_sizes, int n_in,
                              void* d_out, int out_size) {
    const float* x      = (const float*)d_in[0];
    const int*   ei     = (const int*)d_in[1];
    const float* ea     = (const float*)d_in[2];
    const int*   batch  = (const int*)d_in[3];
    const float* Wl0    = (const float*)d_in[4];
    const float* bl0    = (const float*)d_in[5];
    const float* Wr0    = (const float*)d_in[6];
    const float* br0    = (const float*)d_in[7];
    const float* We0    = (const float*)d_in[8];
    const float* att0   = (const float*)d_in[9];
    const float* bias0  = (const float*)d_in[10];
    const float* Wl1    = (const float*)d_in[11];
    const float* bl1    = (const float*)d_in[12];
    const float* Wr1    = (const float*)d_in[13];
    const float* br1    = (const float*)d_in[14];
    const float* We1    = (const float*)d_in[15];
    const float* att1   = (const float*)d_in[16];
    const float* bias1  = (const float*)d_in[17];
    const float* fc1w   = (const float*)d_in[18];
    const float* fc1b   = (const float*)d_in[19];
    const float* fc2w   = (const float*)d_in[20];
    const float* fc2b   = (const float*)d_in[21];
    float* out = (float*)d_out;

    const int pgrid = (Nn * Hh + 255) / 256;              // 12500
    const int g1    = (Ee + 255) / 256;                   // 6250
    const int egrid = (Ee + 16 * CH - 1) / (16 * CH);     // 3125 (exact)
    const int mgrid = (Nn + 63) / 64;                     // 782

    // projections for layer 0 + zero accumulators/cursors
    proj0_kernel<<<pgrid, 256>>>(x, Wl0, bl0, Wr0, br0);
    // counting sort of edges by dst (shared by both layers)
    hist_kernel<<<g1, 256>>>(ei);
    scan_kernel<<<1, 1024>>>();
    scatter_kernel<<<g1, 256>>>(ei, ea);
    // layer 0 edge pass
    edge_sorted_kernel<<<egrid, 256>>>(We0, att0);
    // layer 1 projections (finalize-0 fused; zeroes accumulators behind itself)
    proj1_gemm_kernel<<<mgrid, 256>>>(Wl1, bl1, Wr1, br1, bias0);
    // layer 1 edge pass
    edge_sorted_kernel<<<egrid, 256>>>(We1, att1);
    // pool (finalize-1 fused) + head
    pool_kernel<<<pgrid, 256>>>(batch, bias1);
    head_kernel<<<Gg, FCH>>>(fc1w, fc1b, fc2w, fc2b, out);
}